// round 16
// baseline (speedup 1.0000x reference)
#include <cuda_runtime.h>
#include <cuda_fp16.h>
#include <cstdint>

#define NTOK 4096   // B*L
#define DM   1024
#define DFF  4096
#define SEQ  2048

// ---------------- scratch (device globals: allocation-free) ----------------
__device__ float g_t0[NTOK * DM];
__device__ float g_x1[NTOK * DM];

__device__ __half g_xh[NTOK * DM];
__device__ __half g_qh[NTOK * DM];
__device__ __half g_kh[NTOK * DM];
__device__ __half g_vh[NTOK * DM];
__device__ __half g_ctxh[NTOK * DM];
__device__ __half g_x1h[NTOK * DM];
__device__ __half g_ffh[(size_t)NTOK * DFF];
__device__ __half g_wqkvh[3 * DM * DM];
__device__ float g_bqkv[3 * DM];
__device__ __half g_woh[DM * DM];
__device__ __half g_w1h[(size_t)DFF * DM];
__device__ __half g_w2h[(size_t)DM * DFF];

// ---------------- PTX helpers (family-portable; NO tcgen05) ----------------
__device__ __forceinline__ uint32_t smem_u32(const void* p) {
    uint32_t a;
    asm("{ .reg .u64 t; cvta.to.shared.u64 t, %1; cvt.u32.u64 %0, t; }" : "=r"(a) : "l"(p));
    return a;
}
__device__ __forceinline__ void cpasync16(uint32_t dst, const void* src) {
    asm volatile("cp.async.cg.shared.global [%0], [%1], 16;" :: "r"(dst), "l"(src));
}
__device__ __forceinline__ void ldsm4(uint32_t (&r)[4], uint32_t addr) {
    asm volatile("ldmatrix.sync.aligned.m8n8.x4.shared.b16 {%0,%1,%2,%3}, [%4];"
        : "=r"(r[0]), "=r"(r[1]), "=r"(r[2]), "=r"(r[3]) : "r"(addr));
}
__device__ __forceinline__ void ldsm4t(uint32_t (&r)[4], uint32_t addr) {
    asm volatile("ldmatrix.sync.aligned.m8n8.x4.trans.shared.b16 {%0,%1,%2,%3}, [%4];"
        : "=r"(r[0]), "=r"(r[1]), "=r"(r[2]), "=r"(r[3]) : "r"(addr));
}
__device__ __forceinline__ void mma16816(float (&c)[4], const uint32_t (&a)[4],
                                         uint32_t b0, uint32_t b1) {
    asm volatile("mma.sync.aligned.m16n8k16.row.col.f32.f16.f16.f32 "
        "{%0,%1,%2,%3}, {%4,%5,%6,%7}, {%8,%9}, {%0,%1,%2,%3};"
        : "+f"(c[0]), "+f"(c[1]), "+f"(c[2]), "+f"(c[3])
        : "r"(a[0]), "r"(a[1]), "r"(a[2]), "r"(a[3]), "r"(b0), "r"(b1));
}
__device__ __forceinline__ uint32_t h2u(__half2 v) {
    return *reinterpret_cast<uint32_t*>(&v);
}
__device__ __forceinline__ uint32_t pack2(float a, float b) {
    __half2 h = __floats2half2_rn(a, b);
    return h2u(h);
}
__device__ __forceinline__ uint32_t swz128(uint32_t off) { return off ^ ((off >> 3) & 0x70); }

// =====================================================================
// mma_gemm (persistent, continuous cross-tile pipeline):
// C = A[M,K] @ B[N,K]^T + bias  (fp16 in, fp32 acc)
// CTA tile 256x128, warp tile 64x64, BK=64, 3-stage cp.async keyed by a
// GLOBAL chunk sequence that runs across tile boundaries (no drain).
// epi: 0=none, 1=GELU, 2=+res. fused!=0: QKV routing per 1024-col block.
// =====================================================================
#define ATILEB 32768                  // 256 rows x 128 B
#define BTILEB 16384                  // 128 rows x 128 B
#define GSTAGEB (ATILEB + BTILEB)     // 48 KB
#define SMEM_MMA (3 * GSTAGEB + 1024)

__global__ __launch_bounds__(256, 1)
void mma_gemm(const __half* __restrict__ A, const __half* __restrict__ B,
              const float* __restrict__ bias, const float* __restrict__ res,
              float* __restrict__ Cf,
              __half* __restrict__ Ch0, __half* __restrict__ Ch1,
              __half* __restrict__ Ch2,
              int M, int N, int K, int outN, int epi, int fused,
              int ntiles, int lgnc)
{
    extern __shared__ char smem[];
    const uint32_t s0 = (smem_u32(smem) + 1023) & ~1023u;

    const int tid = threadIdx.x;
    const int wid = tid >> 5, lid = tid & 31;
    const int mw = (wid & 3) << 6;
    const int nw = (wid >> 2) << 6;
    const int nbc = N >> 7;
    const int nchunk = K >> 6;

    const int ar0 = tid >> 1, ar1 = (tid + 256) >> 1;
    const int ah = tid & 1;
    uint32_t swA0[4], swA1[4];
#pragma unroll
    for (int i = 0; i < 4; i++) {
        swA0[i] = swz128(ar0 * 128 + ah * 64 + i * 16);
        swA1[i] = swz128(ar1 * 128 + ah * 64 + i * 16);
    }

    // issue by global sequence number: seq = i*nchunk + c for this CTA's
    // i-th tile (t = blockIdx.x + i*gridDim.x)
    auto issueSeq = [&](int seq) {
        const int i = seq >> lgnc;
        const int c = seq & (nchunk - 1);
        const int t = blockIdx.x + i * (int)gridDim.x;
        if (t >= ntiles) return;
        const int brow = (t / nbc) << 8;
        const int bcol = (t % nbc) << 7;
        const size_t k0 = (size_t)c << 6;
        const size_t ga0 = (size_t)(brow + ar0) * K + ah * 32 + k0;
        const size_t ga1 = (size_t)(brow + ar1) * K + ah * 32 + k0;
        const size_t gb  = (size_t)(bcol + ar0) * K + ah * 32 + k0;
        const uint32_t st = s0 + (uint32_t)(seq % 3) * GSTAGEB;
#pragma unroll
        for (int q = 0; q < 4; q++) {
            cpasync16(st +          swA0[q], A + ga0 + q * 8);
            cpasync16(st +          swA1[q], A + ga1 + q * 8);
            cpasync16(st + ATILEB + swA0[q], B + gb  + q * 8);
        }
    };

    issueSeq(0);
    asm volatile("cp.async.commit_group;");
    issueSeq(1);
    asm volatile("cp.async.commit_group;");

    const int a_row = lid & 15;
    const int a_h   = (lid >> 4) * 16;
    const int b_row = (lid & 7) + ((lid >> 4) << 3);
    const int b_h   = ((lid >> 3) & 1) * 16;
    const int erow = lid >> 2;
    const int ecol = (lid & 3) << 1;

    const int nmy = (ntiles - blockIdx.x + (int)gridDim.x - 1) / (int)gridDim.x;

    for (int i = 0; i < nmy; i++) {
        const int t = blockIdx.x + i * (int)gridDim.x;
        const int brow = (t / nbc) << 8;
        const int bcol = (t % nbc) << 7;

        float acc[4][8][4];
#pragma unroll
        for (int a = 0; a < 4; a++)
#pragma unroll
            for (int j = 0; j < 8; j++)
#pragma unroll
                for (int e = 0; e < 4; e++) acc[a][j][e] = 0.f;

        for (int c = 0; c < nchunk; c++) {
            const int seq = i * nchunk + c;
            asm volatile("cp.async.wait_group 1;");
            __syncthreads();
            issueSeq(seq + 2);
            asm volatile("cp.async.commit_group;");

            const uint32_t st = s0 + (uint32_t)(seq % 3) * GSTAGEB;
            const uint32_t sA = st, sB = st + ATILEB;

#pragma unroll
            for (int ks = 0; ks < 4; ks++) {
                uint32_t af[4][4];
#pragma unroll
                for (int a = 0; a < 4; a++) {
                    uint32_t off = swz128((mw + a * 16 + a_row) * 128 + ks * 32 + a_h);
                    ldsm4(af[a], sA + off);
                }
                uint32_t bf[8][2];
#pragma unroll
                for (int jj = 0; jj < 4; jj++) {
                    uint32_t off = swz128((nw + jj * 16 + b_row) * 128 + ks * 32 + b_h);
                    uint32_t t0[4];
                    ldsm4(t0, sB + off);
                    bf[2*jj][0] = t0[0]; bf[2*jj][1] = t0[1];
                    bf[2*jj+1][0] = t0[2]; bf[2*jj+1][1] = t0[3];
                }
#pragma unroll
                for (int a = 0; a < 4; a++)
#pragma unroll
                    for (int j = 0; j < 8; j++)
                        mma16816(acc[a][j], af[a], bf[j][0], bf[j][1]);
            }
        }

        // ---- epilogue (overlaps next tile's in-flight loads) ----
        int sel = fused ? (bcol >> 10) : 0;
        const int nbase = fused ? (bcol & 1023) : bcol;
        __half* Ch = (sel == 0) ? Ch0 : (sel == 1) ? Ch1 : Ch2;

#pragma unroll
        for (int a = 0; a < 4; a++)
#pragma unroll
            for (int j = 0; j < 8; j++)
#pragma unroll
                for (int h = 0; h < 2; h++) {
                    const int m = brow + mw + a * 16 + erow + h * 8;
                    const int ng = bcol + nw + j * 8 + ecol;
                    const int nl = nbase + nw + j * 8 + ecol;
                    float v0 = acc[a][j][h * 2 + 0] + bias[ng];
                    float v1 = acc[a][j][h * 2 + 1] + bias[ng + 1];
                    const size_t off = (size_t)m * outN + nl;
                    if (epi == 1) {
                        v0 = 0.5f * v0 * (1.0f + erff(v0 * 0.70710678118654752f));
                        v1 = 0.5f * v1 * (1.0f + erff(v1 * 0.70710678118654752f));
                    } else if (epi == 2) {
                        float2 rr = *(const float2*)&res[off];
                        v0 += rr.x; v1 += rr.y;
                    }
                    if (Cf) *(float2*)&Cf[off] = make_float2(v0, v1);
                    if (Ch) *(uint32_t*)&Ch[off] = pack2(v0, v1);
                }
    }
}

// =====================================================================
// Causal flash attention, pure fp16 HMMA, fp32 softmax/accumulators.
// =====================================================================
#define ATT_STAGEB 16384              // K 8K + V 8K per stage
#define SMEM_ATT (1024 + 16384 + 3 * ATT_STAGEB)

__global__ __launch_bounds__(256, 2)
void attn_mma(const __half* __restrict__ Q, const __half* __restrict__ K,
              const __half* __restrict__ V, __half* __restrict__ O_)
{
    extern __shared__ char sm[];
    const uint32_t sQ  = (smem_u32(sm) + 1023) & ~1023u;
    const uint32_t sKV = sQ + 16384;

    const int tid = threadIdx.x, wid = tid >> 5, lid = tid & 31;
    const int qt = (int)gridDim.x - 1 - (int)blockIdx.x;
    const int bh = blockIdx.y;
    const int b = bh >> 4, h = bh & 15;
    const int qbase = qt * 128;
    const size_t tok0 = (size_t)b * SEQ;
    const size_t hoff = (size_t)h * 64;
    const int mw = wid * 16;

    {
        const int r = tid >> 1;
        const int half = tid & 1;
        const size_t g = (tok0 + qbase + r) * DM + hoff + half * 32;
#pragma unroll
        for (int i = 0; i < 4; i++) {
            uint32_t so = swz128(r * 128 + half * 64 + i * 16);
            cpasync16(sQ + so, Q + g + i * 8);
        }
    }

    const int njt = 2 * qt + 2;
    const int kr = tid >> 2;
    const int kq = tid & 3;
    const uint32_t kso0 = swz128(kr * 128 + kq * 32);
    const uint32_t kso1 = swz128(kr * 128 + kq * 32 + 16);

    auto issue_kv = [&](int jt) {
        const uint32_t st = sKV + (uint32_t)(jt % 3) * ATT_STAGEB;
        const size_t g = (tok0 + jt * 64 + kr) * DM + hoff + kq * 16;
        cpasync16(st +        kso0, K + g);
        cpasync16(st +        kso1, K + g + 8);
        cpasync16(st + 8192 + kso0, V + g);
        cpasync16(st + 8192 + kso1, V + g + 8);
    };

    issue_kv(0);
    asm volatile("cp.async.commit_group;");
    issue_kv(1);
    asm volatile("cp.async.commit_group;");

    float O[8][4];
#pragma unroll
    for (int j = 0; j < 8; j++)
#pragma unroll
        for (int e = 0; e < 4; e++) O[j][e] = 0.f;
    float m0 = -1e30f, m1 = -1e30f, l0 = 0.f, l1 = 0.f;

    const int rql = lid >> 2;
    const int cql = (lid & 3) * 2;
    const int row0g = qbase + mw + rql;
    const int row1g = row0g + 8;

    for (int jt = 0; jt < njt; jt++) {
        asm volatile("cp.async.wait_group 1;");
        __syncthreads();
        if (jt + 2 < njt) issue_kv(jt + 2);
        asm volatile("cp.async.commit_group;");

        const bool active = !(mw < 64 && jt == njt - 1);
        if (active) {
            const uint32_t stK = sKV + (uint32_t)(jt % 3) * ATT_STAGEB;
            const uint32_t stV = stK + 8192;

            float S[8][4];
#pragma unroll
            for (int j = 0; j < 8; j++)
#pragma unroll
                for (int e = 0; e < 4; e++) S[j][e] = 0.f;

#pragma unroll
            for (int ks = 0; ks < 4; ks++) {
                uint32_t q4[4];
                uint32_t qoff = swz128((mw + (lid & 15)) * 128 + ks * 32 + (lid >> 4) * 16);
                ldsm4(q4, sQ + qoff);
                uint32_t kf[8][2];
#pragma unroll
                for (int jj = 0; jj < 4; jj++) {
                    uint32_t koff = swz128((jj * 16 + (lid & 7) + ((lid >> 4) << 3)) * 128
                                           + ks * 32 + ((lid >> 3) & 1) * 16);
                    uint32_t t0[4];
                    ldsm4(t0, stK + koff);
                    kf[2*jj][0]=t0[0]; kf[2*jj][1]=t0[1];
                    kf[2*jj+1][0]=t0[2]; kf[2*jj+1][1]=t0[3];
                }
#pragma unroll
                for (int j = 0; j < 8; j++) mma16816(S[j], q4, kf[j][0], kf[j][1]);
            }

            const int colb = jt * 64;
            const bool diag = (jt >= 2 * qt);
#pragma unroll
            for (int j = 0; j < 8; j++)
#pragma unroll
                for (int e = 0; e < 4; e++) {
                    float v = S[j][e] * 0.125f;
                    if (diag) {
                        int col = colb + 8 * j + cql + (e & 1);
                        int row = (e < 2) ? row0g : row1g;
                        if (col > row) v = -1e30f;
                    }
                    S[j][e] = v;
                }

            float rm0 = -1e30f, rm1 = -1e30f;
#pragma unroll
            for (int j = 0; j < 8; j++) {
                rm0 = fmaxf(rm0, fmaxf(S[j][0], S[j][1]));
                rm1 = fmaxf(rm1, fmaxf(S[j][2], S[j][3]));
            }
            rm0 = fmaxf(rm0, __shfl_xor_sync(0xffffffffu, rm0, 1));
            rm0 = fmaxf(rm0, __shfl_xor_sync(0xffffffffu, rm0, 2));
            rm1 = fmaxf(rm1, __shfl_xor_sync(0xffffffffu, rm1, 1));
            rm1 = fmaxf(rm1, __shfl_xor_sync(0xffffffffu, rm1, 2));
            float mn0 = fmaxf(m0, rm0), mn1 = fmaxf(m1, rm1);
            float a0 = __expf(m0 - mn0), a1 = __expf(m1 - mn1);
            m0 = mn0; m1 = mn1;
            float rs0 = 0.f, rs1 = 0.f;
#pragma unroll
            for (int j = 0; j < 8; j++) {
                S[j][0] = __expf(S[j][0] - mn0);
                S[j][1] = __expf(S[j][1] - mn0);
                S[j][2] = __expf(S[j][2] - mn1);
                S[j][3] = __expf(S[j][3] - mn1);
                rs0 += S[j][0] + S[j][1];
                rs1 += S[j][2] + S[j][3];
            }
            rs0 += __shfl_xor_sync(0xffffffffu, rs0, 1);
            rs0 += __shfl_xor_sync(0xffffffffu, rs0, 2);
            rs1 += __shfl_xor_sync(0xffffffffu, rs1, 1);
            rs1 += __shfl_xor_sync(0xffffffffu, rs1, 2);
            l0 = l0 * a0 + rs0;
            l1 = l1 * a1 + rs1;
#pragma unroll
            for (int j = 0; j < 8; j++) {
                O[j][0] *= a0; O[j][1] *= a0; O[j][2] *= a1; O[j][3] *= a1;
            }

            uint32_t pa[4][4];
#pragma unroll
            for (int ks = 0; ks < 4; ks++) {
                pa[ks][0] = pack2(S[2*ks][0],   S[2*ks][1]);
                pa[ks][1] = pack2(S[2*ks][2],   S[2*ks][3]);
                pa[ks][2] = pack2(S[2*ks+1][0], S[2*ks+1][1]);
                pa[ks][3] = pack2(S[2*ks+1][2], S[2*ks+1][3]);
            }

#pragma unroll
            for (int ks = 0; ks < 4; ks++) {
                uint32_t vf[8][2];
                const int rowv = ks * 16 + ((lid >> 3) & 1) * 8 + (lid & 7);
                const int colv = (lid >> 4) * 16;
#pragma unroll
                for (int nb = 0; nb < 4; nb++) {
                    uint32_t voff = swz128(rowv * 128 + nb * 32 + colv);
                    uint32_t t0[4];
                    ldsm4t(t0, stV + voff);
                    vf[2*nb][0]=t0[0]; vf[2*nb][1]=t0[1];
                    vf[2*nb+1][0]=t0[2]; vf[2*nb+1][1]=t0[3];
                }
#pragma unroll
                for (int j = 0; j < 8; j++) mma16816(O[j], pa[ks], vf[j][0], vf[j][1]);
            }
        }
    }

    const float inv0 = 1.0f / l0, inv1 = 1.0f / l1;
    const size_t tq0 = (tok0 + row0g) * DM + hoff;
    const size_t tq1 = (tok0 + row1g) * DM + hoff;
#pragma unroll
    for (int j = 0; j < 8; j++) {
        const int c = 8 * j + cql;
        *(uint32_t*)&O_[tq0 + c] = pack2(O[j][0] * inv0, O[j][1] * inv0);
        *(uint32_t*)&O_[tq1 + c] = pack2(O[j][2] * inv1, O[j][3] * inv1);
    }
}

// =====================================================================
// conversions
// =====================================================================
__global__ __launch_bounds__(256)
void conv_act(const float* __restrict__ in, __half* __restrict__ hi)
{
    const size_t i = ((size_t)blockIdx.x * 256 + threadIdx.x) * 4;
    float4 v = *(const float4*)(in + i);
    *(uint32_t*)&hi[i]     = pack2(v.x, v.y);
    *(uint32_t*)&hi[i + 2] = pack2(v.z, v.w);
}

// combined Wo/W1/W2 transpose -> fp16 [N,K] (one launch)
__global__ __launch_bounds__(256)
void conv_w_all(const float* __restrict__ Wo, const float* __restrict__ W1,
                const float* __restrict__ W2, __half* __restrict__ woh,
                __half* __restrict__ w1h, __half* __restrict__ w2h)
{
    __shared__ float t[32][33];
    const int b = blockIdx.x;
    const float* W; __half* out; int K, N, bx, by;
    if (b < 1024)      { W = Wo; out = woh; K = DM;  N = DM;  bx = b & 31;  by = b >> 5; }
    else if (b < 5120) { int r = b - 1024; W = W1; out = w1h; K = DM;  N = DFF; bx = r & 127; by = r >> 7; }
    else               { int r = b - 5120; W = W2; out = w2h; K = DFF; N = DM;  bx = r & 31;  by = r >> 5; }
    const int n0 = bx * 32, k0 = by * 32;
    const int tx = threadIdx.x & 31, ty = threadIdx.x >> 5;
#pragma unroll
    for (int j = 0; j < 4; j++)
        t[ty + 8 * j][tx] = W[(size_t)(k0 + ty + 8 * j) * N + n0 + tx];
    __syncthreads();
#pragma unroll
    for (int j = 0; j < 4; j++) {
        size_t o = (size_t)(n0 + ty + 8 * j) * K + k0 + tx;
        out[o] = __float2half_rn(t[tx][ty + 8 * j]);
    }
}

// fused QKV weight transpose + bias concat
__global__ __launch_bounds__(256)
void conv_wT3(const float* __restrict__ W0, const float* __restrict__ W1,
              const float* __restrict__ W2, __half* __restrict__ hi,
              const float* __restrict__ b0, const float* __restrict__ b1,
              const float* __restrict__ b2, float* __restrict__ bout)
{
    __shared__ float t[32][33];
    const int n0 = blockIdx.x * 32, k0 = blockIdx.y * 32;
    const int sel = n0 >> 10;
    const int nl = n0 & 1023;
    const float* W = (sel == 0) ? W0 : (sel == 1) ? W1 : W2;
    const int tx = threadIdx.x & 31, ty = threadIdx.x >> 5;
    if (blockIdx.y == 0 && threadIdx.x < 32) {
        const float* bs = (sel == 0) ? b0 : (sel == 1) ? b1 : b2;
        bout[n0 + tx] = bs[nl + tx];
    }
#pragma unroll
    for (int j = 0; j < 4; j++)
        t[ty + 8 * j][tx] = W[(size_t)(k0 + ty + 8 * j) * 1024 + nl + tx];
    __syncthreads();
#pragma unroll
    for (int j = 0; j < 4; j++) {
        size_t o = (size_t)(n0 + ty + 8 * j) * 1024 + k0 + tx;
        hi[o] = __float2half_rn(t[tx][ty + 8 * j]);
    }
}

// =====================================================================
// LayerNorm (+ optional fp16 out)
// =====================================================================
__global__ __launch_bounds__(256)
void ln_kernel(const float* __restrict__ in, const float* __restrict__ gamma,
               const float* __restrict__ beta, float* __restrict__ out,
               __half* __restrict__ oh)
{
    __shared__ float rs[8], rs2[8];
    const int row = blockIdx.x;
    const int t = threadIdx.x;
    float4 v = ((const float4*)(in + (size_t)row * DM))[t];
    float s  = v.x + v.y + v.z + v.w;
    float s2 = v.x * v.x + v.y * v.y + v.z * v.z + v.w * v.w;
#pragma unroll
    for (int off = 16; off; off >>= 1) {
        s  += __shfl_xor_sync(0xffffffffu, s, off);
        s2 += __shfl_xor_sync(0xffffffffu, s2, off);
    }
    if ((t & 31) == 0) { rs[t >> 5] = s; rs2[t >> 5] = s2; }
    __syncthreads();
    float ts = 0.f, ts2 = 0.f;
#pragma unroll
    for (int w = 0; w < 8; w++) { ts += rs[w]; ts2 += rs2[w]; }
    float mu   = ts * (1.0f / DM);
    float var  = ts2 * (1.0f / DM) - mu * mu;
    float rstd = rsqrtf(var + 1e-5f);
    float4 g4 = ((const float4*)gamma)[t];
    float4 b4 = ((const float4*)beta)[t];
    float4 o4;
    o4.x = (v.x - mu) * rstd * g4.x + b4.x;
    o4.y = (v.y - mu) * rstd * g4.y + b4.y;
    o4.z = (v.z - mu) * rstd * g4.z + b4.z;
    o4.w = (v.w - mu) * rstd * g4.w + b4.w;
    ((float4*)(out + (size_t)row * DM))[t] = o4;
    if (oh) {
        const size_t i = (size_t)row * DM + t * 4;
        *(uint32_t*)&oh[i]     = pack2(o4.x, o4.y);
        *(uint32_t*)&oh[i + 2] = pack2(o4.z, o4.w);
    }
}

// =====================================================================
extern "C" void kernel_launch(void* const* d_in, const int* in_sizes, int n_in,
                              void* d_out, int out_size)
{
    (void)in_sizes; (void)n_in; (void)out_size;
    const float* x   = (const float*)d_in[0];
    const float* Wq  = (const float*)d_in[1];
    const float* bq  = (const float*)d_in[2];
    const float* Wk  = (const float*)d_in[3];
    const float* bk  = (const float*)d_in[4];
    const float* Wv  = (const float*)d_in[5];
    const float* bv  = (const float*)d_in[6];
    const float* Wo  = (const float*)d_in[7];
    const float* bo  = (const float*)d_in[8];
    const float* W1  = (const float*)d_in[9];
    const float* b1  = (const float*)d_in[10];
    const float* W2  = (const float*)d_in[11];
    const float* b2  = (const float*)d_in[12];
    const float* g1  = (const float*)d_in[13];
    const float* be1 = (const float*)d_in[14];
    const float* g2  = (const float*)d_in[15];
    const float* be2 = (const float*)d_in[16];
    float* out = (float*)d_out;

    float *gt0, *gx1, *gbqkv;
    cudaGetSymbolAddress((void**)&gt0, g_t0);
    cudaGetSymbolAddress((void**)&gx1, g_x1);
    cudaGetSymbolAddress((void**)&gbqkv, g_bqkv);

    __half *xh, *qh, *kh, *vh, *ctxh, *x1h, *ffh;
    __half *wqkvh, *woh, *w1h, *w2h;
    cudaGetSymbolAddress((void**)&xh,    g_xh);
    cudaGetSymbolAddress((void**)&qh,    g_qh);
    cudaGetSymbolAddress((void**)&kh,    g_kh);
    cudaGetSymbolAddress((void**)&vh,    g_vh);
    cudaGetSymbolAddress((void**)&ctxh,  g_ctxh);
    cudaGetSymbolAddress((void**)&x1h,   g_x1h);
    cudaGetSymbolAddress((void**)&ffh,   g_ffh);
    cudaGetSymbolAddress((void**)&wqkvh, g_wqkvh);
    cudaGetSymbolAddress((void**)&woh,   g_woh);
    cudaGetSymbolAddress((void**)&w1h,   g_w1h);
    cudaGetSymbolAddress((void**)&w2h,   g_w2h);

    cudaFuncSetAttribute(mma_gemm, cudaFuncAttributeMaxDynamicSharedMemorySize, SMEM_MMA);
    cudaFuncSetAttribute(attn_mma, cudaFuncAttributeMaxDynamicSharedMemorySize, SMEM_ATT);

    static cudaStream_t s2 = nullptr;
    static cudaEvent_t evFork = nullptr, evJoin = nullptr;
    if (!s2) {
        cudaStreamCreateWithFlags(&s2, cudaStreamNonBlocking);
        cudaEventCreateWithFlags(&evFork, cudaEventDisableTiming);
        cudaEventCreateWithFlags(&evJoin, cudaEventDisableTiming);
    }

    // ---- critical-path prep ----
    conv_wT3<<<dim3(3 * DM / 32, DM / 32), 256>>>(Wq, Wk, Wv, wqkvh, bq, bk, bv, gbqkv);
    conv_act<<<(NTOK * DM) / 1024, 256>>>(x, xh);

    // ---- fork: combined Wo/W1/W2 prep concurrent with QKV + attention ----
    cudaEventRecord(evFork, 0);
    cudaStreamWaitEvent(s2, evFork, 0);
    conv_w_all<<<9216, 256, 0, s2>>>(Wo, W1, W2, woh, w1h, w2h);
    cudaEventRecord(evJoin, s2);

    // ---- fused QKV GEMM ----
    mma_gemm<<<148, 256, SMEM_MMA>>>(
        xh, wqkvh, gbqkv, nullptr, nullptr,
        qh, kh, vh, NTOK, 3 * DM, DM, DM, 0, 1, 384, 4);

    // ---- attention ----
    attn_mma<<<dim3(SEQ / 128, 32), 256, SMEM_ATT>>>(qh, kh, vh, ctxh);

    // ---- join prep; Wo + residual, LN1 (+fp16) ----
    cudaStreamWaitEvent(0, evJoin, 0);
    mma_gemm<<<128, 256, SMEM_MMA>>>(
        ctxh, woh, bo, x, gt0,
        nullptr, nullptr, nullptr, NTOK, DM, DM, DM, 2, 0, 128, 4);
    ln_kernel<<<NTOK, 256>>>(gt0, g1, be1, gx1, x1h);

    // ---- FFN ----
    mma_gemm<<<148, 256, SMEM_MMA>>>(
        x1h, w1h, b1, nullptr, nullptr,
        ffh, nullptr, nullptr, NTOK, DFF, DM, DFF, 1, 0, 512, 4);
    mma_gemm<<<128, 256, SMEM_MMA>>>(
        ffh, w2h, b2, gx1, gt0,
        nullptr, nullptr, nullptr, NTOK, DM, DFF, DM, 2, 0, 128, 6);
    ln_kernel<<<NTOK, 256>>>(gt0, g2, be2, out, nullptr);
}

// round 17
// speedup vs baseline: 1.0935x; 1.0935x over previous
#include <cuda_runtime.h>
#include <cuda_fp16.h>
#include <cstdint>

#define NTOK 4096   // B*L
#define DM   1024
#define DFF  4096
#define SEQ  2048

// ---------------- scratch (device globals: allocation-free) ----------------
__device__ float g_t0[NTOK * DM];
__device__ float g_x1[NTOK * DM];

__device__ __half g_xh[NTOK * DM];
__device__ __half g_qh[NTOK * DM];
__device__ __half g_kh[NTOK * DM];
__device__ __half g_vh[NTOK * DM];
__device__ __half g_ctxh[NTOK * DM];
__device__ __half g_x1h[NTOK * DM];
__device__ __half g_ffh[(size_t)NTOK * DFF];
__device__ __half g_wqkvh[3 * DM * DM];
__device__ float g_bqkv[3 * DM];
__device__ __half g_woh[DM * DM];
__device__ __half g_w1h[(size_t)DFF * DM];
__device__ __half g_w2h[(size_t)DM * DFF];

// ---------------- PTX helpers (family-portable; NO tcgen05) ----------------
__device__ __forceinline__ uint32_t smem_u32(const void* p) {
    uint32_t a;
    asm("{ .reg .u64 t; cvta.to.shared.u64 t, %1; cvt.u32.u64 %0, t; }" : "=r"(a) : "l"(p));
    return a;
}
__device__ __forceinline__ void cpasync16(uint32_t dst, const void* src) {
    asm volatile("cp.async.cg.shared.global [%0], [%1], 16;" :: "r"(dst), "l"(src));
}
__device__ __forceinline__ void ldsm4(uint32_t (&r)[4], uint32_t addr) {
    asm volatile("ldmatrix.sync.aligned.m8n8.x4.shared.b16 {%0,%1,%2,%3}, [%4];"
        : "=r"(r[0]), "=r"(r[1]), "=r"(r[2]), "=r"(r[3]) : "r"(addr));
}
__device__ __forceinline__ void ldsm4t(uint32_t (&r)[4], uint32_t addr) {
    asm volatile("ldmatrix.sync.aligned.m8n8.x4.trans.shared.b16 {%0,%1,%2,%3}, [%4];"
        : "=r"(r[0]), "=r"(r[1]), "=r"(r[2]), "=r"(r[3]) : "r"(addr));
}
__device__ __forceinline__ void mma16816(float (&c)[4], const uint32_t (&a)[4],
                                         uint32_t b0, uint32_t b1) {
    asm volatile("mma.sync.aligned.m16n8k16.row.col.f32.f16.f16.f32 "
        "{%0,%1,%2,%3}, {%4,%5,%6,%7}, {%8,%9}, {%0,%1,%2,%3};"
        : "+f"(c[0]), "+f"(c[1]), "+f"(c[2]), "+f"(c[3])
        : "r"(a[0]), "r"(a[1]), "r"(a[2]), "r"(a[3]), "r"(b0), "r"(b1));
}
__device__ __forceinline__ uint32_t h2u(__half2 v) {
    return *reinterpret_cast<uint32_t*>(&v);
}
__device__ __forceinline__ uint32_t pack2(float a, float b) {
    __half2 h = __floats2half2_rn(a, b);
    return h2u(h);
}
__device__ __forceinline__ uint32_t swz128(uint32_t off) { return off ^ ((off >> 3) & 0x70); }

// =====================================================================
// mma_gemm: C = A[M,K] @ B[N,K]^T + bias  (fp16 in, fp32 acc)
// CTA tile 128x128, warp tile 64x32 (2m x 4n warps), BK=64, 3-stage
// cp.async, 2 CTAs/SM (launch_bounds(256,2), <=128 regs).
// epi: 0=none, 1=GELU, 2=+res. fused!=0: QKV routing per 1024-col block.
// =====================================================================
#define GTILEB 16384                  // 128 rows x 128 B
#define GSTAGEB (2 * GTILEB)          // A + B = 32 KB
#define SMEM_MMA (3 * GSTAGEB + 1024) // 97 KB -> 2 CTAs/SM

__global__ __launch_bounds__(256, 2)
void mma_gemm(const __half* __restrict__ A, const __half* __restrict__ B,
              const float* __restrict__ bias, const float* __restrict__ res,
              float* __restrict__ Cf,
              __half* __restrict__ Ch0, __half* __restrict__ Ch1,
              __half* __restrict__ Ch2,
              int M, int N, int K, int outN, int epi, int fused)
{
    extern __shared__ char smem[];
    const uint32_t s0 = (smem_u32(smem) + 1023) & ~1023u;

    const int tid = threadIdx.x;
    const int wid = tid >> 5, lid = tid & 31;
    const int brow = blockIdx.y << 7, bcol = blockIdx.x << 7;
    const int mw = (wid & 1) << 6;     // 2 m-warps x 64 rows
    const int nw = (wid >> 1) << 5;    // 4 n-warps x 32 cols

    const int lrow = tid >> 1;
    const int lh   = tid & 1;
    uint32_t sw[4];
#pragma unroll
    for (int i = 0; i < 4; i++)
        sw[i] = swz128(lrow * 128 + lh * 64 + i * 16);
    const size_t ga = (size_t)(brow + lrow) * K + lh * 32;
    const size_t gb = (size_t)(bcol + lrow) * K + lh * 32;

    const int nchunk = K >> 6;

    auto issue = [&](int c) {
        const uint32_t st = s0 + (uint32_t)(c % 3) * GSTAGEB;
        const size_t k0 = (size_t)c << 6;
#pragma unroll
        for (int i = 0; i < 4; i++) {
            cpasync16(st +          sw[i], A + ga + k0 + i * 8);
            cpasync16(st + GTILEB + sw[i], B + gb + k0 + i * 8);
        }
    };

    issue(0);
    asm volatile("cp.async.commit_group;");
    issue(1);
    asm volatile("cp.async.commit_group;");

    float acc[4][4][4];
#pragma unroll
    for (int i = 0; i < 4; i++)
#pragma unroll
        for (int j = 0; j < 4; j++)
#pragma unroll
            for (int e = 0; e < 4; e++) acc[i][j][e] = 0.f;

    const int a_row = lid & 15;
    const int a_h   = (lid >> 4) * 16;
    const int b_row = (lid & 7) + ((lid >> 4) << 3);
    const int b_h   = ((lid >> 3) & 1) * 16;

    for (int c = 0; c < nchunk; c++) {
        asm volatile("cp.async.wait_group 1;");
        __syncthreads();
        if (c + 2 < nchunk) issue(c + 2);
        asm volatile("cp.async.commit_group;");

        const uint32_t st = s0 + (uint32_t)(c % 3) * GSTAGEB;
        const uint32_t sA = st, sB = st + GTILEB;

#pragma unroll
        for (int ks = 0; ks < 4; ks++) {
            uint32_t af[4][4];
#pragma unroll
            for (int i = 0; i < 4; i++) {
                uint32_t off = swz128((mw + i * 16 + a_row) * 128 + ks * 32 + a_h);
                ldsm4(af[i], sA + off);
            }
            uint32_t bf[4][2];
#pragma unroll
            for (int jj = 0; jj < 2; jj++) {
                uint32_t off = swz128((nw + jj * 16 + b_row) * 128 + ks * 32 + b_h);
                uint32_t t0[4];
                ldsm4(t0, sB + off);
                bf[2*jj][0] = t0[0]; bf[2*jj][1] = t0[1];
                bf[2*jj+1][0] = t0[2]; bf[2*jj+1][1] = t0[3];
            }
#pragma unroll
            for (int i = 0; i < 4; i++)
#pragma unroll
                for (int j = 0; j < 4; j++)
                    mma16816(acc[i][j], af[i], bf[j][0], bf[j][1]);
        }
    }

    // ---- epilogue ----
    int sel = fused ? (bcol >> 10) : 0;
    const int nbase = fused ? (bcol & 1023) : bcol;
    __half* Ch = (sel == 0) ? Ch0 : (sel == 1) ? Ch1 : Ch2;

    const int erow = lid >> 2;
    const int ecol = (lid & 3) << 1;
#pragma unroll
    for (int i = 0; i < 4; i++)
#pragma unroll
        for (int j = 0; j < 4; j++)
#pragma unroll
            for (int h = 0; h < 2; h++) {
                const int m = brow + mw + i * 16 + erow + h * 8;
                const int ng = bcol + nw + j * 8 + ecol;
                const int nl = nbase + nw + j * 8 + ecol;
                float v0 = acc[i][j][h * 2 + 0] + bias[ng];
                float v1 = acc[i][j][h * 2 + 1] + bias[ng + 1];
                const size_t off = (size_t)m * outN + nl;
                if (epi == 1) {
                    v0 = 0.5f * v0 * (1.0f + erff(v0 * 0.70710678118654752f));
                    v1 = 0.5f * v1 * (1.0f + erff(v1 * 0.70710678118654752f));
                } else if (epi == 2) {
                    float2 rr = *(const float2*)&res[off];
                    v0 += rr.x; v1 += rr.y;
                }
                if (Cf) *(float2*)&Cf[off] = make_float2(v0, v1);
                if (Ch) *(uint32_t*)&Ch[off] = pack2(v0, v1);
            }
}

// =====================================================================
// Causal flash attention, pure fp16 HMMA, fp32 softmax/accumulators.
// =====================================================================
#define ATT_STAGEB 16384              // K 8K + V 8K per stage
#define SMEM_ATT (1024 + 16384 + 3 * ATT_STAGEB)

__global__ __launch_bounds__(256, 2)
void attn_mma(const __half* __restrict__ Q, const __half* __restrict__ K,
              const __half* __restrict__ V, __half* __restrict__ O_)
{
    extern __shared__ char sm[];
    const uint32_t sQ  = (smem_u32(sm) + 1023) & ~1023u;
    const uint32_t sKV = sQ + 16384;

    const int tid = threadIdx.x, wid = tid >> 5, lid = tid & 31;
    const int qt = (int)gridDim.x - 1 - (int)blockIdx.x;
    const int bh = blockIdx.y;
    const int b = bh >> 4, h = bh & 15;
    const int qbase = qt * 128;
    const size_t tok0 = (size_t)b * SEQ;
    const size_t hoff = (size_t)h * 64;
    const int mw = wid * 16;

    {
        const int r = tid >> 1;
        const int half = tid & 1;
        const size_t g = (tok0 + qbase + r) * DM + hoff + half * 32;
#pragma unroll
        for (int i = 0; i < 4; i++) {
            uint32_t so = swz128(r * 128 + half * 64 + i * 16);
            cpasync16(sQ + so, Q + g + i * 8);
        }
    }

    const int njt = 2 * qt + 2;
    const int kr = tid >> 2;
    const int kq = tid & 3;
    const uint32_t kso0 = swz128(kr * 128 + kq * 32);
    const uint32_t kso1 = swz128(kr * 128 + kq * 32 + 16);

    auto issue_kv = [&](int jt) {
        const uint32_t st = sKV + (uint32_t)(jt % 3) * ATT_STAGEB;
        const size_t g = (tok0 + jt * 64 + kr) * DM + hoff + kq * 16;
        cpasync16(st +        kso0, K + g);
        cpasync16(st +        kso1, K + g + 8);
        cpasync16(st + 8192 + kso0, V + g);
        cpasync16(st + 8192 + kso1, V + g + 8);
    };

    issue_kv(0);
    asm volatile("cp.async.commit_group;");
    issue_kv(1);
    asm volatile("cp.async.commit_group;");

    float O[8][4];
#pragma unroll
    for (int j = 0; j < 8; j++)
#pragma unroll
        for (int e = 0; e < 4; e++) O[j][e] = 0.f;
    float m0 = -1e30f, m1 = -1e30f, l0 = 0.f, l1 = 0.f;

    const int rql = lid >> 2;
    const int cql = (lid & 3) * 2;
    const int row0g = qbase + mw + rql;
    const int row1g = row0g + 8;

    for (int jt = 0; jt < njt; jt++) {
        asm volatile("cp.async.wait_group 1;");
        __syncthreads();
        if (jt + 2 < njt) issue_kv(jt + 2);
        asm volatile("cp.async.commit_group;");

        const bool active = !(mw < 64 && jt == njt - 1);
        if (active) {
            const uint32_t stK = sKV + (uint32_t)(jt % 3) * ATT_STAGEB;
            const uint32_t stV = stK + 8192;

            float S[8][4];
#pragma unroll
            for (int j = 0; j < 8; j++)
#pragma unroll
                for (int e = 0; e < 4; e++) S[j][e] = 0.f;

#pragma unroll
            for (int ks = 0; ks < 4; ks++) {
                uint32_t q4[4];
                uint32_t qoff = swz128((mw + (lid & 15)) * 128 + ks * 32 + (lid >> 4) * 16);
                ldsm4(q4, sQ + qoff);
                uint32_t kf[8][2];
#pragma unroll
                for (int jj = 0; jj < 4; jj++) {
                    uint32_t koff = swz128((jj * 16 + (lid & 7) + ((lid >> 4) << 3)) * 128
                                           + ks * 32 + ((lid >> 3) & 1) * 16);
                    uint32_t t0[4];
                    ldsm4(t0, stK + koff);
                    kf[2*jj][0]=t0[0]; kf[2*jj][1]=t0[1];
                    kf[2*jj+1][0]=t0[2]; kf[2*jj+1][1]=t0[3];
                }
#pragma unroll
                for (int j = 0; j < 8; j++) mma16816(S[j], q4, kf[j][0], kf[j][1]);
            }

            const int colb = jt * 64;
            const bool diag = (jt >= 2 * qt);
#pragma unroll
            for (int j = 0; j < 8; j++)
#pragma unroll
                for (int e = 0; e < 4; e++) {
                    float v = S[j][e] * 0.125f;
                    if (diag) {
                        int col = colb + 8 * j + cql + (e & 1);
                        int row = (e < 2) ? row0g : row1g;
                        if (col > row) v = -1e30f;
                    }
                    S[j][e] = v;
                }

            float rm0 = -1e30f, rm1 = -1e30f;
#pragma unroll
            for (int j = 0; j < 8; j++) {
                rm0 = fmaxf(rm0, fmaxf(S[j][0], S[j][1]));
                rm1 = fmaxf(rm1, fmaxf(S[j][2], S[j][3]));
            }
            rm0 = fmaxf(rm0, __shfl_xor_sync(0xffffffffu, rm0, 1));
            rm0 = fmaxf(rm0, __shfl_xor_sync(0xffffffffu, rm0, 2));
            rm1 = fmaxf(rm1, __shfl_xor_sync(0xffffffffu, rm1, 1));
            rm1 = fmaxf(rm1, __shfl_xor_sync(0xffffffffu, rm1, 2));
            float mn0 = fmaxf(m0, rm0), mn1 = fmaxf(m1, rm1);
            float a0 = __expf(m0 - mn0), a1 = __expf(m1 - mn1);
            m0 = mn0; m1 = mn1;
            float rs0 = 0.f, rs1 = 0.f;
#pragma unroll
            for (int j = 0; j < 8; j++) {
                S[j][0] = __expf(S[j][0] - mn0);
                S[j][1] = __expf(S[j][1] - mn0);
                S[j][2] = __expf(S[j][2] - mn1);
                S[j][3] = __expf(S[j][3] - mn1);
                rs0 += S[j][0] + S[j][1];
                rs1 += S[j][2] + S[j][3];
            }
            rs0 += __shfl_xor_sync(0xffffffffu, rs0, 1);
            rs0 += __shfl_xor_sync(0xffffffffu, rs0, 2);
            rs1 += __shfl_xor_sync(0xffffffffu, rs1, 1);
            rs1 += __shfl_xor_sync(0xffffffffu, rs1, 2);
            l0 = l0 * a0 + rs0;
            l1 = l1 * a1 + rs1;
#pragma unroll
            for (int j = 0; j < 8; j++) {
                O[j][0] *= a0; O[j][1] *= a0; O[j][2] *= a1; O[j][3] *= a1;
            }

            uint32_t pa[4][4];
#pragma unroll
            for (int ks = 0; ks < 4; ks++) {
                pa[ks][0] = pack2(S[2*ks][0],   S[2*ks][1]);
                pa[ks][1] = pack2(S[2*ks][2],   S[2*ks][3]);
                pa[ks][2] = pack2(S[2*ks+1][0], S[2*ks+1][1]);
                pa[ks][3] = pack2(S[2*ks+1][2], S[2*ks+1][3]);
            }

#pragma unroll
            for (int ks = 0; ks < 4; ks++) {
                uint32_t vf[8][2];
                const int rowv = ks * 16 + ((lid >> 3) & 1) * 8 + (lid & 7);
                const int colv = (lid >> 4) * 16;
#pragma unroll
                for (int nb = 0; nb < 4; nb++) {
                    uint32_t voff = swz128(rowv * 128 + nb * 32 + colv);
                    uint32_t t0[4];
                    ldsm4t(t0, stV + voff);
                    vf[2*nb][0]=t0[0]; vf[2*nb][1]=t0[1];
                    vf[2*nb+1][0]=t0[2]; vf[2*nb+1][1]=t0[3];
                }
#pragma unroll
                for (int j = 0; j < 8; j++) mma16816(O[j], pa[ks], vf[j][0], vf[j][1]);
            }
        }
    }

    const float inv0 = 1.0f / l0, inv1 = 1.0f / l1;
    const size_t tq0 = (tok0 + row0g) * DM + hoff;
    const size_t tq1 = (tok0 + row1g) * DM + hoff;
#pragma unroll
    for (int j = 0; j < 8; j++) {
        const int c = 8 * j + cql;
        *(uint32_t*)&O_[tq0 + c] = pack2(O[j][0] * inv0, O[j][1] * inv0);
        *(uint32_t*)&O_[tq1 + c] = pack2(O[j][2] * inv1, O[j][3] * inv1);
    }
}

// =====================================================================
// conversions
// =====================================================================
__global__ __launch_bounds__(256)
void conv_act(const float* __restrict__ in, __half* __restrict__ hi)
{
    const size_t i = ((size_t)blockIdx.x * 256 + threadIdx.x) * 4;
    float4 v = *(const float4*)(in + i);
    *(uint32_t*)&hi[i]     = pack2(v.x, v.y);
    *(uint32_t*)&hi[i + 2] = pack2(v.z, v.w);
}

// combined Wo/W1/W2 transpose -> fp16 [N,K] (one launch)
__global__ __launch_bounds__(256)
void conv_w_all(const float* __restrict__ Wo, const float* __restrict__ W1,
                const float* __restrict__ W2, __half* __restrict__ woh,
                __half* __restrict__ w1h, __half* __restrict__ w2h)
{
    __shared__ float t[32][33];
    const int b = blockIdx.x;
    const float* W; __half* out; int K, N, bx, by;
    if (b < 1024)      { W = Wo; out = woh; K = DM;  N = DM;  bx = b & 31;  by = b >> 5; }
    else if (b < 5120) { int r = b - 1024; W = W1; out = w1h; K = DM;  N = DFF; bx = r & 127; by = r >> 7; }
    else               { int r = b - 5120; W = W2; out = w2h; K = DFF; N = DM;  bx = r & 31;  by = r >> 5; }
    const int n0 = bx * 32, k0 = by * 32;
    const int tx = threadIdx.x & 31, ty = threadIdx.x >> 5;
#pragma unroll
    for (int j = 0; j < 4; j++)
        t[ty + 8 * j][tx] = W[(size_t)(k0 + ty + 8 * j) * N + n0 + tx];
    __syncthreads();
#pragma unroll
    for (int j = 0; j < 4; j++) {
        size_t o = (size_t)(n0 + ty + 8 * j) * K + k0 + tx;
        out[o] = __float2half_rn(t[tx][ty + 8 * j]);
    }
}

// fused QKV weight transpose + bias concat
__global__ __launch_bounds__(256)
void conv_wT3(const float* __restrict__ W0, const float* __restrict__ W1,
              const float* __restrict__ W2, __half* __restrict__ hi,
              const float* __restrict__ b0, const float* __restrict__ b1,
              const float* __restrict__ b2, float* __restrict__ bout)
{
    __shared__ float t[32][33];
    const int n0 = blockIdx.x * 32, k0 = blockIdx.y * 32;
    const int sel = n0 >> 10;
    const int nl = n0 & 1023;
    const float* W = (sel == 0) ? W0 : (sel == 1) ? W1 : W2;
    const int tx = threadIdx.x & 31, ty = threadIdx.x >> 5;
    if (blockIdx.y == 0 && threadIdx.x < 32) {
        const float* bs = (sel == 0) ? b0 : (sel == 1) ? b1 : b2;
        bout[n0 + tx] = bs[nl + tx];
    }
#pragma unroll
    for (int j = 0; j < 4; j++)
        t[ty + 8 * j][tx] = W[(size_t)(k0 + ty + 8 * j) * 1024 + nl + tx];
    __syncthreads();
#pragma unroll
    for (int j = 0; j < 4; j++) {
        size_t o = (size_t)(n0 + ty + 8 * j) * 1024 + k0 + tx;
        hi[o] = __float2half_rn(t[tx][ty + 8 * j]);
    }
}

// =====================================================================
// LayerNorm (+ optional fp16 out)
// =====================================================================
__global__ __launch_bounds__(256)
void ln_kernel(const float* __restrict__ in, const float* __restrict__ gamma,
               const float* __restrict__ beta, float* __restrict__ out,
               __half* __restrict__ oh)
{
    __shared__ float rs[8], rs2[8];
    const int row = blockIdx.x;
    const int t = threadIdx.x;
    float4 v = ((const float4*)(in + (size_t)row * DM))[t];
    float s  = v.x + v.y + v.z + v.w;
    float s2 = v.x * v.x + v.y * v.y + v.z * v.z + v.w * v.w;
#pragma unroll
    for (int off = 16; off; off >>= 1) {
        s  += __shfl_xor_sync(0xffffffffu, s, off);
        s2 += __shfl_xor_sync(0xffffffffu, s2, off);
    }
    if ((t & 31) == 0) { rs[t >> 5] = s; rs2[t >> 5] = s2; }
    __syncthreads();
    float ts = 0.f, ts2 = 0.f;
#pragma unroll
    for (int w = 0; w < 8; w++) { ts += rs[w]; ts2 += rs2[w]; }
    float mu   = ts * (1.0f / DM);
    float var  = ts2 * (1.0f / DM) - mu * mu;
    float rstd = rsqrtf(var + 1e-5f);
    float4 g4 = ((const float4*)gamma)[t];
    float4 b4 = ((const float4*)beta)[t];
    float4 o4;
    o4.x = (v.x - mu) * rstd * g4.x + b4.x;
    o4.y = (v.y - mu) * rstd * g4.y + b4.y;
    o4.z = (v.z - mu) * rstd * g4.z + b4.z;
    o4.w = (v.w - mu) * rstd * g4.w + b4.w;
    ((float4*)(out + (size_t)row * DM))[t] = o4;
    if (oh) {
        const size_t i = (size_t)row * DM + t * 4;
        *(uint32_t*)&oh[i]     = pack2(o4.x, o4.y);
        *(uint32_t*)&oh[i + 2] = pack2(o4.z, o4.w);
    }
}

// =====================================================================
extern "C" void kernel_launch(void* const* d_in, const int* in_sizes, int n_in,
                              void* d_out, int out_size)
{
    (void)in_sizes; (void)n_in; (void)out_size;
    const float* x   = (const float*)d_in[0];
    const float* Wq  = (const float*)d_in[1];
    const float* bq  = (const float*)d_in[2];
    const float* Wk  = (const float*)d_in[3];
    const float* bk  = (const float*)d_in[4];
    const float* Wv  = (const float*)d_in[5];
    const float* bv  = (const float*)d_in[6];
    const float* Wo  = (const float*)d_in[7];
    const float* bo  = (const float*)d_in[8];
    const float* W1  = (const float*)d_in[9];
    const float* b1  = (const float*)d_in[10];
    const float* W2  = (const float*)d_in[11];
    const float* b2  = (const float*)d_in[12];
    const float* g1  = (const float*)d_in[13];
    const float* be1 = (const float*)d_in[14];
    const float* g2  = (const float*)d_in[15];
    const float* be2 = (const float*)d_in[16];
    float* out = (float*)d_out;

    float *gt0, *gx1, *gbqkv;
    cudaGetSymbolAddress((void**)&gt0, g_t0);
    cudaGetSymbolAddress((void**)&gx1, g_x1);
    cudaGetSymbolAddress((void**)&gbqkv, g_bqkv);

    __half *xh, *qh, *kh, *vh, *ctxh, *x1h, *ffh;
    __half *wqkvh, *woh, *w1h, *w2h;
    cudaGetSymbolAddress((void**)&xh,    g_xh);
    cudaGetSymbolAddress((void**)&qh,    g_qh);
    cudaGetSymbolAddress((void**)&kh,    g_kh);
    cudaGetSymbolAddress((void**)&vh,    g_vh);
    cudaGetSymbolAddress((void**)&ctxh,  g_ctxh);
    cudaGetSymbolAddress((void**)&x1h,   g_x1h);
    cudaGetSymbolAddress((void**)&ffh,   g_ffh);
    cudaGetSymbolAddress((void**)&wqkvh, g_wqkvh);
    cudaGetSymbolAddress((void**)&woh,   g_woh);
    cudaGetSymbolAddress((void**)&w1h,   g_w1h);
    cudaGetSymbolAddress((void**)&w2h,   g_w2h);

    cudaFuncSetAttribute(mma_gemm, cudaFuncAttributeMaxDynamicSharedMemorySize, SMEM_MMA);
    cudaFuncSetAttribute(attn_mma, cudaFuncAttributeMaxDynamicSharedMemorySize, SMEM_ATT);

    static cudaStream_t s2 = nullptr;
    static cudaEvent_t evFork = nullptr, evJoin = nullptr;
    if (!s2) {
        cudaStreamCreateWithFlags(&s2, cudaStreamNonBlocking);
        cudaEventCreateWithFlags(&evFork, cudaEventDisableTiming);
        cudaEventCreateWithFlags(&evJoin, cudaEventDisableTiming);
    }

    // ---- critical-path prep ----
    conv_wT3<<<dim3(3 * DM / 32, DM / 32), 256>>>(Wq, Wk, Wv, wqkvh, bq, bk, bv, gbqkv);
    conv_act<<<(NTOK * DM) / 1024, 256>>>(x, xh);

    // ---- fork: combined Wo/W1/W2 prep concurrent with QKV + attention ----
    cudaEventRecord(evFork, 0);
    cudaStreamWaitEvent(s2, evFork, 0);
    conv_w_all<<<9216, 256, 0, s2>>>(Wo, W1, W2, woh, w1h, w2h);
    cudaEventRecord(evJoin, s2);

    // ---- fused QKV GEMM (N=3072) ----
    mma_gemm<<<dim3(3 * DM / 128, NTOK / 128), 256, SMEM_MMA>>>(
        xh, wqkvh, gbqkv, nullptr, nullptr,
        qh, kh, vh, NTOK, 3 * DM, DM, DM, 0, 1);

    // ---- attention ----
    attn_mma<<<dim3(SEQ / 128, 32), 256, SMEM_ATT>>>(qh, kh, vh, ctxh);

    // ---- join prep; Wo + residual, LN1 (+fp16) ----
    cudaStreamWaitEvent(0, evJoin, 0);
    mma_gemm<<<dim3(DM / 128, NTOK / 128), 256, SMEM_MMA>>>(
        ctxh, woh, bo, x, gt0,
        nullptr, nullptr, nullptr, NTOK, DM, DM, DM, 2, 0);
    ln_kernel<<<NTOK, 256>>>(gt0, g1, be1, gx1, x1h);

    // ---- FFN ----
    mma_gemm<<<dim3(DFF / 128, NTOK / 128), 256, SMEM_MMA>>>(
        x1h, w1h, b1, nullptr, nullptr,
        ffh, nullptr, nullptr, NTOK, DFF, DM, DFF, 1, 0);
    mma_gemm<<<dim3(DM / 128, NTOK / 128), 256, SMEM_MMA>>>(
        ffh, w2h, b2, gx1, gt0,
        nullptr, nullptr, nullptr, NTOK, DM, DFF, DM, 2, 0);
    ln_kernel<<<NTOK, 256>>>(gt0, g2, be2, out, nullptr);
}